// round 15
// baseline (speedup 1.0000x reference)
#include <cuda_runtime.h>
#include <cuda_fp16.h>
#include <cstdint>

// Problem constants: N=50000, E=800000, IN=128, OUT=200
#define NN   50000
#define FD   128
#define OD   200
#define CAP  96
#define MT   128
#define NT   391                   // M tiles (128 rows each)
// A operand image (fp16): [tile][chunk ks 0..7][row 0..127][48B], 32B data + 16B pad
#define AROW   48
#define ACH    (MT * AROW)         // 6144 B per chunk
#define ATILE  (8 * ACH)           // 49152 B per tile
#define AELEMS ((size_t)NT * ATILE / 2)
// B (weight) image (fp16): [k 0..127][216 cols] row 432B; chunk = 16 rows = 6912B
#define BCOLS  216
#define BROW   (BCOLS * 2)         // 432
#define BCH    (16 * BROW)         // 6912
#define BELEMS ((size_t)FD * BCOLS)
#define SLOTS  16                  // ring depth: 2 full K-blocks in flight
#define GW     16                  // GEMM warps (512 threads)

// ================= device scratch (no cudaMalloc allowed) ================
__device__ float d_deg[NN];
__device__ int   d_cnt[NN];
__device__ int2  d_bkt[(size_t)NN * CAP];     // packed (src, norm-as-int)
// row-major fp16 copies for gathers (256B per node row)
__device__ __align__(16) __half d_xh[(size_t)NN * FD];
__device__ __align__(16) __half d_t1h[(size_t)NN * FD];
// chunk-major fp16 operand images of tx0(x), tx1, tx2 (zero-init covers pad rows)
__device__ __align__(1024) __half d_a[3][AELEMS];
// weights fp16, order: w1_0, w2_0, w2_1, w3_0, w3_1, w3_2
__device__ __align__(1024) __half d_wh[6][BELEMS];

// ================= helpers ==============================================
__device__ __forceinline__ uint32_t smem_u32(const void* p) {
    uint32_t a;
    asm("{ .reg .u64 t; cvta.to.shared.u64 t, %1; cvt.u32.u64 %0, t; }" : "=r"(a) : "l"(p));
    return a;
}
#define MBARRIER_INIT(mb, c) \
    asm volatile("mbarrier.init.shared.b64 [%0], %1;" :: "r"((uint32_t)(mb)), "r"((uint32_t)(c)) : "memory")
#define MBARRIER_EXPECT_TX(mb, tx) \
    asm volatile("mbarrier.arrive.expect_tx.shared.b64 _, [%0], %1;" :: "r"((uint32_t)(mb)), "r"((uint32_t)(tx)) : "memory")
#define MBARRIER_ARRIVE(mb) \
    asm volatile("mbarrier.arrive.shared.b64 _, [%0];" :: "r"((uint32_t)(mb)) : "memory")
#define BULK_G2S(dst, src, bytes, mb) \
    asm volatile("cp.async.bulk.shared::cta.global.mbarrier::complete_tx::bytes [%0], [%1], %2, [%3];" \
        :: "r"((uint32_t)(dst)), "l"(src), "r"((uint32_t)(bytes)), "r"((uint32_t)(mb)) : "memory")
#define MBARRIER_WAIT_PARITY(mb, ph) do {                                        \
    uint32_t _mb = (uint32_t)(mb), _ph = (uint32_t)(ph), _done;                  \
    asm volatile("{\n\t.reg .pred p;\n\t"                                        \
        "mbarrier.try_wait.parity.acquire.cta.shared::cta.b64 p, [%1], %2;\n\t"  \
        "selp.b32 %0, 1, 0, p;\n\t}" : "=r"(_done) : "r"(_mb), "r"(_ph) : "memory"); \
    if (!_done) {                                                                \
        asm volatile("{\n\t.reg .pred P1;\n\t"                                   \
            "W%=:\n\t"                                                           \
            "mbarrier.try_wait.parity.acquire.cta.shared::cta.b64 P1, [%0], %1, 0x989680;\n\t" \
            "@P1 bra.uni D%=;\n\t"                                               \
            "bra.uni W%=;\n\t"                                                   \
            "D%=:\n\t}" :: "r"(_mb), "r"(_ph) : "memory");                       \
    }                                                                            \
} while (0)

__device__ __forceinline__ void ldsm4(uint32_t* r, uint32_t addr) {
    asm volatile("ldmatrix.sync.aligned.m8n8.x4.shared.b16 {%0,%1,%2,%3}, [%4];"
                 : "=r"(r[0]), "=r"(r[1]), "=r"(r[2]), "=r"(r[3]) : "r"(addr));
}
__device__ __forceinline__ void ldsm4t(uint32_t* r, uint32_t addr) {
    asm volatile("ldmatrix.sync.aligned.m8n8.x4.trans.shared.b16 {%0,%1,%2,%3}, [%4];"
                 : "=r"(r[0]), "=r"(r[1]), "=r"(r[2]), "=r"(r[3]) : "r"(addr));
}
__device__ __forceinline__ void mma16816(float* c, const uint32_t* a, const uint32_t* b) {
    asm volatile("mma.sync.aligned.m16n8k16.row.col.f32.f16.f16.f32 "
                 "{%0,%1,%2,%3}, {%4,%5,%6,%7}, {%8,%9}, {%0,%1,%2,%3};"
                 : "+f"(c[0]), "+f"(c[1]), "+f"(c[2]), "+f"(c[3])
                 : "r"(a[0]), "r"(a[1]), "r"(a[2]), "r"(a[3]), "r"(b[0]), "r"(b[1]));
}

// ================= graph preprocessing ==================================
__global__ void deg_kernel(const int* __restrict__ src, const float* __restrict__ w, int E) {
    int e = blockIdx.x * blockDim.x + threadIdx.x;
    if (e < E) atomicAdd(&d_deg[src[e]], w[e]);
}
__global__ void fill_kernel(const int* __restrict__ src, const int* __restrict__ dst,
                            const float* __restrict__ w, int E) {
    int e = blockIdx.x * blockDim.x + threadIdx.x;
    if (e >= E) return;
    int s = src[e], d = dst[e];
    float ds = d_deg[s], dd = d_deg[d];
    float is = ds > 0.f ? rsqrtf(ds) : 0.f;
    float id = dd > 0.f ? rsqrtf(dd) : 0.f;
    float nrm = -is * w[e] * id;
    int slot = atomicAdd(&d_cnt[d], 1);
    if (slot < CAP)
        d_bkt[(size_t)d * CAP + slot] = make_int2(s, __float_as_int(nrm));
}

// pack a float4 to fp16 uint2
__device__ __forceinline__ uint2 pack_h4(float4 v) {
    __half2 p0 = __floats2half2_rn(v.x, v.y);
    __half2 p1 = __floats2half2_rn(v.z, v.w);
    return make_uint2(*(uint32_t*)&p0, *(uint32_t*)&p1);
}
// store a float4 (features l*4..l*4+3 of one node row) into op's fp16 A image
__device__ __forceinline__ void store_a4(int op, int node, int l, float4 v) {
    int tile = node >> 7, r = node & 127, ks = l >> 2;
    size_t e = ((size_t)(tile * 8 + ks) * MT + r) * 24 + (l & 3) * 4;
    *(uint2*)&d_a[op][e] = pack_h4(v);
}
// unpack uint2 (4 fp16) -> float4
__device__ __forceinline__ float4 unpack_h4(uint2 u) {
    float2 f0 = __half22float2(*(__half2*)&u.x);
    float2 f1 = __half22float2(*(__half2*)&u.y);
    return make_float4(f0.x, f0.y, f1.x, f1.y);
}

// x fp32 -> x_h row-major fp16 + A image op0
__global__ void convert_x_kernel(const float4* __restrict__ x4, int nwords) {
    int i = blockIdx.x * blockDim.x + threadIdx.x;
    if (i >= nwords) return;
    int node = i >> 5, l = i & 31;
    float4 v = x4[i];
    ((uint2*)d_xh)[i] = pack_h4(v);
    store_a4(0, node, l, v);
}

// weights fp32 [k=128][n=200] -> fp16 [k=128][n=216] zero padded
__global__ void wprep_kernel(const float* w0, const float* w1, const float* w2,
                             const float* w3, const float* w4, const float* w5) {
    const float* ws[6] = {w0, w1, w2, w3, w4, w5};
    int i = blockIdx.x * blockDim.x + threadIdx.x;
    if (i >= 6 * FD * BCOLS) return;
    int m = i / (FD * BCOLS);
    int r = i % (FD * BCOLS);
    int k = r / BCOLS, n = r % BCOLS;
    float v = (n < OD) ? ws[m][(size_t)k * OD + n] : 0.f;
    d_wh[m][r] = __float2half_rn(v);
}

// gather SpMM (fp16 gather, fp32 accumulate), warp-per-node, 4 features/lane, MLP=8.
// MODE 0: tx1 = L^x    -> t1h row-major + A image op1   (gathers d_xh)
// MODE 1: tx2 = 2 L^ tx1 - x -> A image op2             (gathers d_t1h)
template <int MODE>
__global__ __launch_bounds__(256) void spmm_kernel(const float* __restrict__ x, int nnodes) {
    __shared__ int   ssrc[8][CAP];
    __shared__ float snrm[8][CAP];
    int w = threadIdx.x >> 5, l = threadIdx.x & 31;
    int node = blockIdx.x * 8 + w;
    if (node >= nnodes) return;

    int cnt = d_cnt[node];
    if (cnt > CAP) cnt = CAP;
    for (int j = l; j < cnt; j += 32) {
        int2 b = d_bkt[(size_t)node * CAP + j];
        ssrc[w][j] = b.x;
        snrm[w][j] = __int_as_float(b.y);
    }
    __syncwarp();

    const uint2* g = (MODE == 0) ? (const uint2*)d_xh : (const uint2*)d_t1h;
    float4 acc = make_float4(0.f, 0.f, 0.f, 0.f);
    int j = 0;
    for (; j + 8 <= cnt; j += 8) {
        uint2 u0 = g[(size_t)ssrc[w][j+0] * 32 + l];
        uint2 u1 = g[(size_t)ssrc[w][j+1] * 32 + l];
        uint2 u2 = g[(size_t)ssrc[w][j+2] * 32 + l];
        uint2 u3 = g[(size_t)ssrc[w][j+3] * 32 + l];
        uint2 u4 = g[(size_t)ssrc[w][j+4] * 32 + l];
        uint2 u5 = g[(size_t)ssrc[w][j+5] * 32 + l];
        uint2 u6 = g[(size_t)ssrc[w][j+6] * 32 + l];
        uint2 u7 = g[(size_t)ssrc[w][j+7] * 32 + l];
        float4 v0 = unpack_h4(u0), v1 = unpack_h4(u1), v2 = unpack_h4(u2), v3 = unpack_h4(u3);
        float4 v4 = unpack_h4(u4), v5 = unpack_h4(u5), v6 = unpack_h4(u6), v7 = unpack_h4(u7);
        float n0 = snrm[w][j+0], n1 = snrm[w][j+1], n2 = snrm[w][j+2], n3 = snrm[w][j+3];
        float n4 = snrm[w][j+4], n5 = snrm[w][j+5], n6 = snrm[w][j+6], n7 = snrm[w][j+7];
        acc.x += n0*v0.x + n1*v1.x + n2*v2.x + n3*v3.x + n4*v4.x + n5*v5.x + n6*v6.x + n7*v7.x;
        acc.y += n0*v0.y + n1*v1.y + n2*v2.y + n3*v3.y + n4*v4.y + n5*v5.y + n6*v6.y + n7*v7.y;
        acc.z += n0*v0.z + n1*v1.z + n2*v2.z + n3*v3.z + n4*v4.z + n5*v5.z + n6*v6.z + n7*v7.z;
        acc.w += n0*v0.w + n1*v1.w + n2*v2.w + n3*v3.w + n4*v4.w + n5*v5.w + n6*v6.w + n7*v7.w;
    }
    for (; j < cnt; j++) {
        float4 v = unpack_h4(g[(size_t)ssrc[w][j] * 32 + l]);
        float n0 = snrm[w][j];
        acc.x += n0*v.x; acc.y += n0*v.y; acc.z += n0*v.z; acc.w += n0*v.w;
    }

    if (MODE == 0) {
        ((uint2*)d_t1h)[(size_t)node * 32 + l] = pack_h4(acc);
        store_a4(1, node, l, acc);
    } else {
        float4 xv = ((const float4*)x)[(size_t)node * 32 + l];
        float4 t = make_float4(2.f*acc.x - xv.x, 2.f*acc.y - xv.y,
                               2.f*acc.z - xv.z, 2.f*acc.w - xv.w);
        store_a4(2, node, l, t);
    }
}

// ==== deep-ring mma.sync GEMM (fp16, MT=128, 16 slots, 512 threads) ======
#define SA     0
#define SB     (SLOTS * ACH)               // 98304
#define S_BIAS (SB + SLOTS * BCH)          // 208896
#define S_MBF  (S_BIAS + 896)              // full barriers, 16 x 8B
#define S_MBE  (S_MBF + 128)               // empty barriers, 16 x 8B
#define S_TOTAL (S_MBE + 128)              // 210048

// warp tile: 16 rows x 104 cols (wm 0..7, wn 0..1)
__device__ __forceinline__ void consume_chunk(uint32_t sb, int slot, int l,
                                              int mbase, int nbase,
                                              float acc[13][4]) {
    uint32_t a[4], bb[14][2];
    uint32_t aBase = sb + SA + slot * ACH;
    ldsm4(a, aBase + (mbase + (l & 15)) * AROW + (l >> 4) * 16);
    uint32_t bBase = sb + SB + slot * BCH + (l & 15) * BROW + (l >> 4) * 16;
#pragma unroll
    for (int j2 = 0; j2 < 7; j2++)
        ldsm4t(&bb[j2 * 2][0], bBase + (nbase + j2 * 16) * 2);
#pragma unroll
    for (int j = 0; j < 13; j++) mma16816(acc[j], a, bb[j]);
}

// issue the 2 bulk copies for global chunk index t into slot (t & 15); single lane
__device__ __forceinline__ void issue_chunk(uint32_t sb, int t, int tile, int wbase) {
    int kb = t >> 3, c = t & 7;
    int slot = t & (SLOTS - 1);
    const char* ga  = (const char*)d_a[kb] + (size_t)tile * ATILE + c * ACH;
    const char* gb  = (const char*)d_wh[wbase + kb] + c * BCH;
    uint32_t mb = sb + S_MBF + slot * 8;
    MBARRIER_EXPECT_TX(mb, ACH + BCH);
    BULK_G2S(sb + SA + slot * ACH, ga, ACH, mb);
    BULK_G2S(sb + SB + slot * BCH, gb, BCH, mb);
}

__global__ __launch_bounds__(512, 1) void gemm_kernel(
    const float* __restrict__ b1, const float* __restrict__ b2, const float* __restrict__ b3,
    float* __restrict__ out, int nnodes)
{
    extern __shared__ char smem[];
    const uint32_t sb = smem_u32(smem);
    const int tid = threadIdx.x;
    const int l = tid & 31;
    const int wid = tid >> 5;
    const int s = blockIdx.y;
    const int tile = blockIdx.x;
    const int bm = tile * MT;
    const int T = 8 * (s + 1);           // total chunks (8, 16, 24)
    const int wbase = s * (s + 1) / 2;
    float* sbias = (float*)(smem + S_BIAS);

    const float* bp = (s == 0) ? b1 : (s == 1) ? b2 : b3;
    if (tid < OD) sbias[tid] = bp[tid];
    if (tid == 0) {
#pragma unroll
        for (int c = 0; c < SLOTS; c++) {
            MBARRIER_INIT(sb + S_MBF + c * 8, 1);    // full: tx-completed
            MBARRIER_INIT(sb + S_MBE + c * 8, GW);   // empty: one arrive per warp
        }
    }
    __syncthreads();

    // prologue: fill up to SLOTS slots (single lane; non-blocking issues)
    const int P = (T < SLOTS) ? T : SLOTS;
    if (tid == 0)
        for (int t = 0; t < P; t++) issue_chunk(sb, t, tile, wbase);

    const int wm = wid >> 1, wn = wid & 1;
    const int mbase = wm * 16, nbase = wn * 104;

    float acc[13][4];
#pragma unroll
    for (int j = 0; j < 13; j++)
#pragma unroll
        for (int r = 0; r < 4; r++) acc[j][r] = 0.f;

    for (int t = 0; t < T; t++) {
        int slot = t & (SLOTS - 1);
        int use  = t >> 4;
        MBARRIER_WAIT_PARITY(sb + S_MBF + slot * 8, use & 1);
        consume_chunk(sb, slot, l, mbase, nbase, acc);
        __syncwarp();
        if (l == 0) MBARRIER_ARRIVE(sb + S_MBE + slot * 8);
        // Producer: WHOLE warp 0 executes the blocking empty-wait (warp-uniform,
        // no divergent spin against the next collective); only lane 0 issues.
        if (wid == 0 && t + SLOTS < T) {
            MBARRIER_WAIT_PARITY(sb + S_MBE + slot * 8, use & 1);
            if (l == 0) issue_chunk(sb, t + SLOTS, tile, wbase);
        }
        __syncwarp();
    }

    // epilogue: warp covers rows [bm+mbase, bm+mbase+16)
    {
        int row0 = bm + mbase + (l >> 2);
#pragma unroll
        for (int j = 0; j < 13; j++) {
            int col = nbase + j * 8 + (l & 3) * 2;
            if (col >= OD) continue;
            float bc0 = sbias[col], bc1 = sbias[col + 1];
            if (row0 < nnodes) {
                float2 v = make_float2(acc[j][0] + bc0, acc[j][1] + bc1);
                *(float2*)(out + ((size_t)s * nnodes + row0) * OD + col) = v;
            }
            int row1 = row0 + 8;
            if (row1 < nnodes) {
                float2 v = make_float2(acc[j][2] + bc0, acc[j][3] + bc1);
                *(float2*)(out + ((size_t)s * nnodes + row1) * OD + col) = v;
            }
        }
    }
}

static inline int cdiv(int a, int b) { return (a + b - 1) / b; }

extern "C" void kernel_launch(void* const* d_in, const int* in_sizes, int n_in,
                              void* d_out, int out_size) {
    const float* x    = (const float*)d_in[0];
    const int*   ei   = (const int*)  d_in[1];
    const float* ew   = (const float*)d_in[2];
    const float* w1_0 = (const float*)d_in[3];
    const float* b1   = (const float*)d_in[4];
    const float* w2_0 = (const float*)d_in[5];
    const float* w2_1 = (const float*)d_in[6];
    const float* b2   = (const float*)d_in[7];
    const float* w3_0 = (const float*)d_in[8];
    const float* w3_1 = (const float*)d_in[9];
    const float* w3_2 = (const float*)d_in[10];
    const float* b3   = (const float*)d_in[11];
    float* out = (float*)d_out;

    int E = in_sizes[2];
    int N = in_sizes[0] / FD;
    if (N > NN) N = NN;
    const int* src = ei;
    const int* dst = ei + E;

    static void* p_deg = nullptr;
    static void* p_cnt = nullptr;
    if (!p_deg) {
        cudaFuncSetAttribute(gemm_kernel, cudaFuncAttributeMaxDynamicSharedMemorySize, S_TOTAL);
        cudaGetSymbolAddress(&p_deg, d_deg);
        cudaGetSymbolAddress(&p_cnt, d_cnt);
    }

    cudaMemsetAsync(p_deg, 0, sizeof(float) * NN);
    cudaMemsetAsync(p_cnt, 0, sizeof(int) * NN);
    deg_kernel<<<cdiv(E, 256), 256>>>(src, ew, E);
    fill_kernel<<<cdiv(E, 256), 256>>>(src, dst, ew, E);
    convert_x_kernel<<<cdiv(N * 32, 256), 256>>>((const float4*)x, N * 32);
    wprep_kernel<<<cdiv(6 * FD * BCOLS, 256), 256>>>(w1_0, w2_0, w2_1, w3_0, w3_1, w3_2);
    spmm_kernel<0><<<cdiv(N, 8), 256>>>(x, N);
    spmm_kernel<1><<<cdiv(N, 8), 256>>>(x, N);

    dim3 grid(NT, 3);
    gemm_kernel<<<grid, 512, S_TOTAL>>>(b1, b2, b3, out, N);
}

// round 16
// speedup vs baseline: 1.0773x; 1.0773x over previous
#include <cuda_runtime.h>
#include <cuda_fp16.h>
#include <cstdint>

// Problem constants: N=50000, E=800000, IN=128, OUT=200
#define NN   50000
#define FD   128
#define OD   200
#define CAP  96
#define MT   128
#define NT   391                   // M tiles (128 rows each)
// A operand image (fp16): [tile][chunk ks 0..7][row 0..127][48B], 32B data + 16B pad
#define AROW   48
#define ACH    (MT * AROW)         // 6144 B per chunk
#define ATILE  (8 * ACH)           // 49152 B per tile
#define AELEMS ((size_t)NT * ATILE / 2)
// B (weight) image (fp16): [k 0..127][216 cols] row 432B; chunk = 16 rows = 6912B
#define BCOLS  216
#define BROW   (BCOLS * 2)         // 432
#define BCH    (16 * BROW)         // 6912
#define BELEMS ((size_t)FD * BCOLS)
#define SLOTS  16                  // ring depth: 2 full K-blocks in flight

// ================= device scratch (no cudaMalloc allowed) ================
__device__ float d_deg[NN];
__device__ int   d_cnt[NN];
__device__ int2  d_bkt[(size_t)NN * CAP];     // packed (src, norm-as-int)
// row-major fp16 copies for gathers (256B per node row)
__device__ __align__(16) __half d_xh[(size_t)NN * FD];
__device__ __align__(16) __half d_t1h[(size_t)NN * FD];
// chunk-major fp16 operand images of tx0(x), tx1, tx2 (zero-init covers pad rows)
__device__ __align__(1024) __half d_a[3][AELEMS];
// weights fp16, order: w1_0, w2_0, w2_1, w3_0, w3_1, w3_2
__device__ __align__(1024) __half d_wh[6][BELEMS];

// ================= helpers ==============================================
__device__ __forceinline__ uint32_t smem_u32(const void* p) {
    uint32_t a;
    asm("{ .reg .u64 t; cvta.to.shared.u64 t, %1; cvt.u32.u64 %0, t; }" : "=r"(a) : "l"(p));
    return a;
}
#define MBARRIER_INIT(mb, c) \
    asm volatile("mbarrier.init.shared.b64 [%0], %1;" :: "r"((uint32_t)(mb)), "r"((uint32_t)(c)) : "memory")
#define MBARRIER_EXPECT_TX(mb, tx) \
    asm volatile("mbarrier.arrive.expect_tx.shared.b64 _, [%0], %1;" :: "r"((uint32_t)(mb)), "r"((uint32_t)(tx)) : "memory")
#define MBARRIER_ARRIVE(mb) \
    asm volatile("mbarrier.arrive.shared.b64 _, [%0];" :: "r"((uint32_t)(mb)) : "memory")
#define BULK_G2S(dst, src, bytes, mb) \
    asm volatile("cp.async.bulk.shared::cta.global.mbarrier::complete_tx::bytes [%0], [%1], %2, [%3];" \
        :: "r"((uint32_t)(dst)), "l"(src), "r"((uint32_t)(bytes)), "r"((uint32_t)(mb)) : "memory")
#define MBARRIER_WAIT_PARITY(mb, ph) do {                                        \
    uint32_t _mb = (uint32_t)(mb), _ph = (uint32_t)(ph), _done;                  \
    asm volatile("{\n\t.reg .pred p;\n\t"                                        \
        "mbarrier.try_wait.parity.acquire.cta.shared::cta.b64 p, [%1], %2;\n\t"  \
        "selp.b32 %0, 1, 0, p;\n\t}" : "=r"(_done) : "r"(_mb), "r"(_ph) : "memory"); \
    if (!_done) {                                                                \
        asm volatile("{\n\t.reg .pred P1;\n\t"                                   \
            "W%=:\n\t"                                                           \
            "mbarrier.try_wait.parity.acquire.cta.shared::cta.b64 P1, [%0], %1, 0x989680;\n\t" \
            "@P1 bra.uni D%=;\n\t"                                               \
            "bra.uni W%=;\n\t"                                                   \
            "D%=:\n\t}" :: "r"(_mb), "r"(_ph) : "memory");                       \
    }                                                                            \
} while (0)

__device__ __forceinline__ void ldsm4(uint32_t* r, uint32_t addr) {
    asm volatile("ldmatrix.sync.aligned.m8n8.x4.shared.b16 {%0,%1,%2,%3}, [%4];"
                 : "=r"(r[0]), "=r"(r[1]), "=r"(r[2]), "=r"(r[3]) : "r"(addr));
}
__device__ __forceinline__ void ldsm4t(uint32_t* r, uint32_t addr) {
    asm volatile("ldmatrix.sync.aligned.m8n8.x4.trans.shared.b16 {%0,%1,%2,%3}, [%4];"
                 : "=r"(r[0]), "=r"(r[1]), "=r"(r[2]), "=r"(r[3]) : "r"(addr));
}
__device__ __forceinline__ void mma16816(float* c, const uint32_t* a, const uint32_t* b) {
    asm volatile("mma.sync.aligned.m16n8k16.row.col.f32.f16.f16.f32 "
                 "{%0,%1,%2,%3}, {%4,%5,%6,%7}, {%8,%9}, {%0,%1,%2,%3};"
                 : "+f"(c[0]), "+f"(c[1]), "+f"(c[2]), "+f"(c[3])
                 : "r"(a[0]), "r"(a[1]), "r"(a[2]), "r"(a[3]), "r"(b[0]), "r"(b[1]));
}

// pack a float4 to fp16 uint2
__device__ __forceinline__ uint2 pack_h4(float4 v) {
    __half2 p0 = __floats2half2_rn(v.x, v.y);
    __half2 p1 = __floats2half2_rn(v.z, v.w);
    return make_uint2(*(uint32_t*)&p0, *(uint32_t*)&p1);
}
// store a float4 (features l*4..l*4+3 of one node row) into op's fp16 A image
__device__ __forceinline__ void store_a4(int op, int node, int l, float4 v) {
    int tile = node >> 7, r = node & 127, ks = l >> 2;
    size_t e = ((size_t)(tile * 8 + ks) * MT + r) * 24 + (l & 3) * 4;
    *(uint2*)&d_a[op][e] = pack_h4(v);
}
// unpack uint2 (4 fp16) -> float4
__device__ __forceinline__ float4 unpack_h4(uint2 u) {
    float2 f0 = __half22float2(*(__half2*)&u.x);
    float2 f1 = __half22float2(*(__half2*)&u.y);
    return make_float4(f0.x, f0.y, f1.x, f1.y);
}

// ================= fused prep: deg + convert_x + wprep ==================
// blockIdx.x ranges: [0, degB) -> deg; [degB, degB+cvtB) -> convert; rest -> wprep
__global__ void prep_kernel(const int* __restrict__ src, const float* __restrict__ ew, int E,
                            const float4* __restrict__ x4, int nwords,
                            const float* w0, const float* w1, const float* w2,
                            const float* w3, const float* w4, const float* w5,
                            int degB, int cvtB) {
    int b = blockIdx.x;
    if (b < degB) {
        int e = b * 256 + threadIdx.x;
        if (e < E) atomicAdd(&d_deg[src[e]], ew[e]);
    } else if (b < degB + cvtB) {
        int i = (b - degB) * 256 + threadIdx.x;
        if (i < nwords) {
            int node = i >> 5, l = i & 31;
            float4 v = x4[i];
            ((uint2*)d_xh)[i] = pack_h4(v);
            store_a4(0, node, l, v);
        }
    } else {
        const float* ws[6] = {w0, w1, w2, w3, w4, w5};
        int i = (b - degB - cvtB) * 256 + threadIdx.x;
        if (i < 6 * FD * BCOLS) {
            int m = i / (FD * BCOLS);
            int r = i % (FD * BCOLS);
            int k = r / BCOLS, n = r % BCOLS;
            float v = (n < OD) ? ws[m][(size_t)k * OD + n] : 0.f;
            d_wh[m][r] = __float2half_rn(v);
        }
    }
}

__global__ void fill_kernel(const int* __restrict__ src, const int* __restrict__ dst,
                            const float* __restrict__ w, int E) {
    int e = blockIdx.x * blockDim.x + threadIdx.x;
    if (e >= E) return;
    int s = src[e], d = dst[e];
    float ds = d_deg[s], dd = d_deg[d];
    float is = ds > 0.f ? rsqrtf(ds) : 0.f;
    float id = dd > 0.f ? rsqrtf(dd) : 0.f;
    float nrm = -is * w[e] * id;
    int slot = atomicAdd(&d_cnt[d], 1);
    if (slot < CAP)
        d_bkt[(size_t)d * CAP + slot] = make_int2(s, __float_as_int(nrm));
}

// gather SpMM (fp16 gather, fp32 accumulate), warp-per-node, 4 features/lane, MLP=8.
// MODE 0: tx1 = L^x    -> t1h row-major + A image op1   (gathers d_xh)
// MODE 1: tx2 = 2 L^ tx1 - x -> A image op2             (gathers d_t1h)
template <int MODE>
__global__ __launch_bounds__(256) void spmm_kernel(const float* __restrict__ x, int nnodes) {
    __shared__ int   ssrc[8][CAP];
    __shared__ float snrm[8][CAP];
    int w = threadIdx.x >> 5, l = threadIdx.x & 31;
    int node = blockIdx.x * 8 + w;
    if (node >= nnodes) return;

    int cnt = d_cnt[node];
    if (cnt > CAP) cnt = CAP;
    for (int j = l; j < cnt; j += 32) {
        int2 b = d_bkt[(size_t)node * CAP + j];
        ssrc[w][j] = b.x;
        snrm[w][j] = __int_as_float(b.y);
    }
    __syncwarp();

    const uint2* g = (MODE == 0) ? (const uint2*)d_xh : (const uint2*)d_t1h;
    float4 acc = make_float4(0.f, 0.f, 0.f, 0.f);
    int j = 0;
    for (; j + 8 <= cnt; j += 8) {
        uint2 u0 = g[(size_t)ssrc[w][j+0] * 32 + l];
        uint2 u1 = g[(size_t)ssrc[w][j+1] * 32 + l];
        uint2 u2 = g[(size_t)ssrc[w][j+2] * 32 + l];
        uint2 u3 = g[(size_t)ssrc[w][j+3] * 32 + l];
        uint2 u4 = g[(size_t)ssrc[w][j+4] * 32 + l];
        uint2 u5 = g[(size_t)ssrc[w][j+5] * 32 + l];
        uint2 u6 = g[(size_t)ssrc[w][j+6] * 32 + l];
        uint2 u7 = g[(size_t)ssrc[w][j+7] * 32 + l];
        float4 v0 = unpack_h4(u0), v1 = unpack_h4(u1), v2 = unpack_h4(u2), v3 = unpack_h4(u3);
        float4 v4 = unpack_h4(u4), v5 = unpack_h4(u5), v6 = unpack_h4(u6), v7 = unpack_h4(u7);
        float n0 = snrm[w][j+0], n1 = snrm[w][j+1], n2 = snrm[w][j+2], n3 = snrm[w][j+3];
        float n4 = snrm[w][j+4], n5 = snrm[w][j+5], n6 = snrm[w][j+6], n7 = snrm[w][j+7];
        acc.x += n0*v0.x + n1*v1.x + n2*v2.x + n3*v3.x + n4*v4.x + n5*v5.x + n6*v6.x + n7*v7.x;
        acc.y += n0*v0.y + n1*v1.y + n2*v2.y + n3*v3.y + n4*v4.y + n5*v5.y + n6*v6.y + n7*v7.y;
        acc.z += n0*v0.z + n1*v1.z + n2*v2.z + n3*v3.z + n4*v4.z + n5*v5.z + n6*v6.z + n7*v7.z;
        acc.w += n0*v0.w + n1*v1.w + n2*v2.w + n3*v3.w + n4*v4.w + n5*v5.w + n6*v6.w + n7*v7.w;
    }
    for (; j < cnt; j++) {
        float4 v = unpack_h4(g[(size_t)ssrc[w][j] * 32 + l]);
        float n0 = snrm[w][j];
        acc.x += n0*v.x; acc.y += n0*v.y; acc.z += n0*v.z; acc.w += n0*v.w;
    }

    if (MODE == 0) {
        ((uint2*)d_t1h)[(size_t)node * 32 + l] = pack_h4(acc);
        store_a4(1, node, l, acc);
    } else {
        float4 xv = ((const float4*)x)[(size_t)node * 32 + l];
        float4 t = make_float4(2.f*acc.x - xv.x, 2.f*acc.y - xv.y,
                               2.f*acc.z - xv.z, 2.f*acc.w - xv.w);
        store_a4(2, node, l, t);
    }
}

// ============ deep-ring mma.sync GEMM (fp16, MT=128, 16 slots) ===========
#define SA     0
#define SB     (SLOTS * ACH)               // 98304
#define S_BIAS (SB + SLOTS * BCH)          // 208896
#define S_MBF  (S_BIAS + 896)              // full barriers, 16 x 8B
#define S_MBE  (S_MBF + 128)               // empty barriers, 16 x 8B
#define S_TOTAL (S_MBE + 128)              // 210048

__device__ __forceinline__ void consume_chunk(uint32_t sb, int slot, int l,
                                              int mbase, int nbase,
                                              float acc[2][13][4]) {
    uint32_t a[2][4], bb[14][2];
    uint32_t aBase = sb + SA + slot * ACH;
#pragma unroll
    for (int i = 0; i < 2; i++)
        ldsm4(a[i], aBase + (mbase + i * 16 + (l & 15)) * AROW + (l >> 4) * 16);
    uint32_t bBase = sb + SB + slot * BCH + (l & 15) * BROW + (l >> 4) * 16;
#pragma unroll
    for (int j2 = 0; j2 < 7; j2++)
        ldsm4t(&bb[j2 * 2][0], bBase + (nbase + j2 * 16) * 2);
#pragma unroll
    for (int i = 0; i < 2; i++)
#pragma unroll
        for (int j = 0; j < 13; j++) mma16816(acc[i][j], a[i], bb[j]);
}

// issue the 2 bulk copies for global chunk index t into slot (t & 15); single lane
__device__ __forceinline__ void issue_chunk(uint32_t sb, int t, int tile, int wbase) {
    int kb = t >> 3, c = t & 7;
    int slot = t & (SLOTS - 1);
    const char* ga  = (const char*)d_a[kb] + (size_t)tile * ATILE + c * ACH;
    const char* gb  = (const char*)d_wh[wbase + kb] + c * BCH;
    uint32_t mb = sb + S_MBF + slot * 8;
    MBARRIER_EXPECT_TX(mb, ACH + BCH);
    BULK_G2S(sb + SA + slot * ACH, ga, ACH, mb);
    BULK_G2S(sb + SB + slot * BCH, gb, BCH, mb);
}

__global__ __launch_bounds__(256, 1) void gemm_kernel(
    const float* __restrict__ b1, const float* __restrict__ b2, const float* __restrict__ b3,
    float* __restrict__ out, int nnodes)
{
    extern __shared__ char smem[];
    const uint32_t sb = smem_u32(smem);
    const int tid = threadIdx.x;
    const int l = tid & 31;
    const int wid = tid >> 5;
    const int s = blockIdx.y;
    const int tile = blockIdx.x;
    const int bm = tile * MT;
    const int T = 8 * (s + 1);           // total chunks (8, 16, 24)
    const int wbase = s * (s + 1) / 2;
    float* sbias = (float*)(smem + S_BIAS);

    const float* bp = (s == 0) ? b1 : (s == 1) ? b2 : b3;
    if (tid < OD) sbias[tid] = bp[tid];
    if (tid == 0) {
#pragma unroll
        for (int c = 0; c < SLOTS; c++) {
            MBARRIER_INIT(sb + S_MBF + c * 8, 1);   // full: tx-completed
            MBARRIER_INIT(sb + S_MBE + c * 8, 8);   // empty: one arrive per warp
        }
    }
    __syncthreads();

    // prologue: fill up to SLOTS slots (single lane; non-blocking issues)
    const int P = (T < SLOTS) ? T : SLOTS;
    if (tid == 0)
        for (int t = 0; t < P; t++) issue_chunk(sb, t, tile, wbase);

    const int wm = wid >> 1, wn = wid & 1;
    const int mbase = wm * 32, nbase = wn * 104;

    float acc[2][13][4];
#pragma unroll
    for (int i = 0; i < 2; i++)
#pragma unroll
        for (int j = 0; j < 13; j++)
#pragma unroll
            for (int r = 0; r < 4; r++) acc[i][j][r] = 0.f;

    for (int t = 0; t < T; t++) {
        int slot = t & (SLOTS - 1);
        int use  = t >> 4;
        MBARRIER_WAIT_PARITY(sb + S_MBF + slot * 8, use & 1);
        consume_chunk(sb, slot, l, mbase, nbase, acc);
        __syncwarp();
        if (l == 0) MBARRIER_ARRIVE(sb + S_MBE + slot * 8);
        // Producer: WHOLE warp 0 executes the blocking empty-wait (warp-uniform,
        // no divergent spin against the next collective); only lane 0 issues.
        if (wid == 0 && t + SLOTS < T) {
            MBARRIER_WAIT_PARITY(sb + S_MBE + slot * 8, use & 1);
            if (l == 0) issue_chunk(sb, t + SLOTS, tile, wbase);
        }
        __syncwarp();
    }

    // epilogue
#pragma unroll
    for (int i = 0; i < 2; i++) {
        int row0 = bm + mbase + i * 16 + (l >> 2);
#pragma unroll
        for (int j = 0; j < 13; j++) {
            int col = nbase + j * 8 + (l & 3) * 2;
            if (col >= OD) continue;
            float bc0 = sbias[col], bc1 = sbias[col + 1];
            if (row0 < nnodes) {
                float2 v = make_float2(acc[i][j][0] + bc0, acc[i][j][1] + bc1);
                *(float2*)(out + ((size_t)s * nnodes + row0) * OD + col) = v;
            }
            int row1 = row0 + 8;
            if (row1 < nnodes) {
                float2 v = make_float2(acc[i][j][2] + bc0, acc[i][j][3] + bc1);
                *(float2*)(out + ((size_t)s * nnodes + row1) * OD + col) = v;
            }
        }
    }
}

static inline int cdiv(int a, int b) { return (a + b - 1) / b; }

extern "C" void kernel_launch(void* const* d_in, const int* in_sizes, int n_in,
                              void* d_out, int out_size) {
    const float* x    = (const float*)d_in[0];
    const int*   ei   = (const int*)  d_in[1];
    const float* ew   = (const float*)d_in[2];
    const float* w1_0 = (const float*)d_in[3];
    const float* b1   = (const float*)d_in[4];
    const float* w2_0 = (const float*)d_in[5];
    const float* w2_1 = (const float*)d_in[6];
    const float* b2   = (const float*)d_in[7];
    const float* w3_0 = (const float*)d_in[8];
    const float* w3_1 = (const float*)d_in[9];
    const float* w3_2 = (const float*)d_in[10];
    const float* b3   = (const float*)d_in[11];
    float* out = (float*)d_out;

    int E = in_sizes[2];
    int N = in_sizes[0] / FD;
    if (N > NN) N = NN;
    const int* src = ei;
    const int* dst = ei + E;

    static void* p_deg = nullptr;
    static void* p_cnt = nullptr;
    if (!p_deg) {
        cudaFuncSetAttribute(gemm_kernel, cudaFuncAttributeMaxDynamicSharedMemorySize, S_TOTAL);
        cudaGetSymbolAddress(&p_deg, d_deg);
        cudaGetSymbolAddress(&p_cnt, d_cnt);
    }

    cudaMemsetAsync(p_deg, 0, sizeof(float) * NN);
    cudaMemsetAsync(p_cnt, 0, sizeof(int) * NN);

    int degB = cdiv(E, 256);
    int cvtB = cdiv(N * 32, 256);
    int wprB = cdiv(6 * FD * BCOLS, 256);
    prep_kernel<<<degB + cvtB + wprB, 256>>>(src, ew, E, (const float4*)x, N * 32,
                                             w1_0, w2_0, w2_1, w3_0, w3_1, w3_2,
                                             degB, cvtB);
    fill_kernel<<<cdiv(E, 256), 256>>>(src, dst, ew, E);
    spmm_kernel<0><<<cdiv(N, 8), 256>>>(x, N);
    spmm_kernel<1><<<cdiv(N, 8), 256>>>(x, N);

    dim3 grid(NT, 3);
    gemm_kernel<<<grid, 256, S_TOTAL>>>(b1, b2, b3, out, N);
}

// round 17
// speedup vs baseline: 1.0901x; 1.0118x over previous
#include <cuda_runtime.h>
#include <cuda_fp16.h>
#include <cstdint>

// Problem constants: N=50000, E=800000, IN=128, OUT=200
#define NN   50000
#define FD   128
#define OD   200
#define CAP  96
#define MT   128
#define NT   391                   // M tiles (128 rows each)
// A operand image (fp16): [tile][chunk ks 0..7][row 0..127][48B], 32B data + 16B pad
#define AROW   48
#define ACH    (MT * AROW)         // 6144 B per chunk
#define ATILE  (8 * ACH)           // 49152 B per tile
#define AELEMS ((size_t)NT * ATILE / 2)
// B (weight) image (fp16): [k 0..127][216 cols] row 432B; chunk = 16 rows = 6912B
#define BCOLS  216
#define BROW   (BCOLS * 2)         // 432
#define BCH    (16 * BROW)         // 6912
#define BELEMS ((size_t)FD * BCOLS)
#define SLOTS  16                  // ring depth: 2 full K-blocks in flight

// ================= device scratch (no cudaMalloc allowed) ================
__device__ float d_deg[NN];
__device__ int   d_cnt[NN];
__device__ int2  d_bkt[(size_t)NN * CAP];     // packed (src-byte-offset, norm-as-int)
// row-major fp16 copies for gathers (256B per node row)
__device__ __align__(16) __half d_xh[(size_t)NN * FD];
__device__ __align__(16) __half d_t1h[(size_t)NN * FD];
// chunk-major fp16 operand images of tx0(x), tx1, tx2 (zero-init covers pad rows)
__device__ __align__(1024) __half d_a[3][AELEMS];
// weights fp16, order: w1_0, w2_0, w2_1, w3_0, w3_1, w3_2
__device__ __align__(1024) __half d_wh[6][BELEMS];

// ================= helpers ==============================================
__device__ __forceinline__ uint32_t smem_u32(const void* p) {
    uint32_t a;
    asm("{ .reg .u64 t; cvta.to.shared.u64 t, %1; cvt.u32.u64 %0, t; }" : "=r"(a) : "l"(p));
    return a;
}
#define MBARRIER_INIT(mb, c) \
    asm volatile("mbarrier.init.shared.b64 [%0], %1;" :: "r"((uint32_t)(mb)), "r"((uint32_t)(c)) : "memory")
#define MBARRIER_EXPECT_TX(mb, tx) \
    asm volatile("mbarrier.arrive.expect_tx.shared.b64 _, [%0], %1;" :: "r"((uint32_t)(mb)), "r"((uint32_t)(tx)) : "memory")
#define MBARRIER_ARRIVE(mb) \
    asm volatile("mbarrier.arrive.shared.b64 _, [%0];" :: "r"((uint32_t)(mb)) : "memory")
#define BULK_G2S(dst, src, bytes, mb) \
    asm volatile("cp.async.bulk.shared::cta.global.mbarrier::complete_tx::bytes [%0], [%1], %2, [%3];" \
        :: "r"((uint32_t)(dst)), "l"(src), "r"((uint32_t)(bytes)), "r"((uint32_t)(mb)) : "memory")
#define MBARRIER_WAIT_PARITY(mb, ph) do {                                        \
    uint32_t _mb = (uint32_t)(mb), _ph = (uint32_t)(ph), _done;                  \
    asm volatile("{\n\t.reg .pred p;\n\t"                                        \
        "mbarrier.try_wait.parity.acquire.cta.shared::cta.b64 p, [%1], %2;\n\t"  \
        "selp.b32 %0, 1, 0, p;\n\t}" : "=r"(_done) : "r"(_mb), "r"(_ph) : "memory"); \
    if (!_done) {                                                                \
        asm volatile("{\n\t.reg .pred P1;\n\t"                                   \
            "W%=:\n\t"                                                           \
            "mbarrier.try_wait.parity.acquire.cta.shared::cta.b64 P1, [%0], %1, 0x989680;\n\t" \
            "@P1 bra.uni D%=;\n\t"                                               \
            "bra.uni W%=;\n\t"                                                   \
            "D%=:\n\t}" :: "r"(_mb), "r"(_ph) : "memory");                       \
    }                                                                            \
} while (0)

__device__ __forceinline__ void ldsm4(uint32_t* r, uint32_t addr) {
    asm volatile("ldmatrix.sync.aligned.m8n8.x4.shared.b16 {%0,%1,%2,%3}, [%4];"
                 : "=r"(r[0]), "=r"(r[1]), "=r"(r[2]), "=r"(r[3]) : "r"(addr));
}
__device__ __forceinline__ void ldsm4t(uint32_t* r, uint32_t addr) {
    asm volatile("ldmatrix.sync.aligned.m8n8.x4.trans.shared.b16 {%0,%1,%2,%3}, [%4];"
                 : "=r"(r[0]), "=r"(r[1]), "=r"(r[2]), "=r"(r[3]) : "r"(addr));
}
__device__ __forceinline__ void mma16816(float* c, const uint32_t* a, const uint32_t* b) {
    asm volatile("mma.sync.aligned.m16n8k16.row.col.f32.f16.f16.f32 "
                 "{%0,%1,%2,%3}, {%4,%5,%6,%7}, {%8,%9}, {%0,%1,%2,%3};"
                 : "+f"(c[0]), "+f"(c[1]), "+f"(c[2]), "+f"(c[3])
                 : "r"(a[0]), "r"(a[1]), "r"(a[2]), "r"(a[3]), "r"(b[0]), "r"(b[1]));
}

// pack a float4 to fp16 uint2
__device__ __forceinline__ uint2 pack_h4(float4 v) {
    __half2 p0 = __floats2half2_rn(v.x, v.y);
    __half2 p1 = __floats2half2_rn(v.z, v.w);
    return make_uint2(*(uint32_t*)&p0, *(uint32_t*)&p1);
}
// store a float4 (features l*4..l*4+3 of one node row) into op's fp16 A image
__device__ __forceinline__ void store_a4(int op, int node, int l, float4 v) {
    int tile = node >> 7, r = node & 127, ks = l >> 2;
    size_t e = ((size_t)(tile * 8 + ks) * MT + r) * 24 + (l & 3) * 4;
    *(uint2*)&d_a[op][e] = pack_h4(v);
}
// unpack uint2 (4 fp16) -> float4
__device__ __forceinline__ float4 unpack_h4(uint2 u) {
    float2 f0 = __half22float2(*(__half2*)&u.x);
    float2 f1 = __half22float2(*(__half2*)&u.y);
    return make_float4(f0.x, f0.y, f1.x, f1.y);
}

// ================= fused prep: deg + convert_x + wprep ==================
__global__ void prep_kernel(const int* __restrict__ src, const float* __restrict__ ew, int E,
                            const float4* __restrict__ x4, int nwords,
                            const float* w0, const float* w1, const float* w2,
                            const float* w3, const float* w4, const float* w5,
                            int degB, int cvtB) {
    int b = blockIdx.x;
    if (b < degB) {
        int e = b * 256 + threadIdx.x;
        if (e < E) atomicAdd(&d_deg[src[e]], ew[e]);
    } else if (b < degB + cvtB) {
        int i = (b - degB) * 256 + threadIdx.x;
        if (i < nwords) {
            int node = i >> 5, l = i & 31;
            float4 v = x4[i];
            ((uint2*)d_xh)[i] = pack_h4(v);
            store_a4(0, node, l, v);
        }
    } else {
        const float* ws[6] = {w0, w1, w2, w3, w4, w5};
        int i = (b - degB - cvtB) * 256 + threadIdx.x;
        if (i < 6 * FD * BCOLS) {
            int m = i / (FD * BCOLS);
            int r = i % (FD * BCOLS);
            int k = r / BCOLS, n = r % BCOLS;
            float v = (n < OD) ? ws[m][(size_t)k * OD + n] : 0.f;
            d_wh[m][r] = __float2half_rn(v);
        }
    }
}

__global__ void fill_kernel(const int* __restrict__ src, const int* __restrict__ dst,
                            const float* __restrict__ w, int E) {
    int e = blockIdx.x * blockDim.x + threadIdx.x;
    if (e >= E) return;
    int s = src[e], d = dst[e];
    float ds = d_deg[s], dd = d_deg[d];
    float is = ds > 0.f ? rsqrtf(ds) : 0.f;
    float id = dd > 0.f ? rsqrtf(dd) : 0.f;
    float nrm = -is * w[e] * id;
    int slot = atomicAdd(&d_cnt[d], 1);
    if (slot < CAP)
        d_bkt[(size_t)d * CAP + slot] = make_int2(s << 8, __float_as_int(nrm));  // byte offset
}

// gather SpMM (fp16 gather, fp32 accumulate), warp-per-node, 4 features/lane, MLP=8.
// buckets carry pre-multiplied byte offsets (node*256).
template <int MODE>
__global__ __launch_bounds__(256) void spmm_kernel(const float* __restrict__ x, int nnodes) {
    __shared__ int   ssrc[8][CAP];
    __shared__ float snrm[8][CAP];
    int w = threadIdx.x >> 5, l = threadIdx.x & 31;
    int node = blockIdx.x * 8 + w;
    if (node >= nnodes) return;

    int cnt = d_cnt[node];
    if (cnt > CAP) cnt = CAP;
    for (int j = l; j < cnt; j += 32) {
        int2 b = d_bkt[(size_t)node * CAP + j];
        ssrc[w][j] = b.x;
        snrm[w][j] = __int_as_float(b.y);
    }
    __syncwarp();

    const char* g = (MODE == 0) ? (const char*)d_xh : (const char*)d_t1h;
    const char* gl = g + l * 8;
    float4 acc = make_float4(0.f, 0.f, 0.f, 0.f);
    int j = 0;
    for (; j + 8 <= cnt; j += 8) {
        uint2 u0 = *(const uint2*)(gl + ssrc[w][j+0]);
        uint2 u1 = *(const uint2*)(gl + ssrc[w][j+1]);
        uint2 u2 = *(const uint2*)(gl + ssrc[w][j+2]);
        uint2 u3 = *(const uint2*)(gl + ssrc[w][j+3]);
        uint2 u4 = *(const uint2*)(gl + ssrc[w][j+4]);
        uint2 u5 = *(const uint2*)(gl + ssrc[w][j+5]);
        uint2 u6 = *(const uint2*)(gl + ssrc[w][j+6]);
        uint2 u7 = *(const uint2*)(gl + ssrc[w][j+7]);
        float4 v0 = unpack_h4(u0), v1 = unpack_h4(u1), v2 = unpack_h4(u2), v3 = unpack_h4(u3);
        float4 v4 = unpack_h4(u4), v5 = unpack_h4(u5), v6 = unpack_h4(u6), v7 = unpack_h4(u7);
        float n0 = snrm[w][j+0], n1 = snrm[w][j+1], n2 = snrm[w][j+2], n3 = snrm[w][j+3];
        float n4 = snrm[w][j+4], n5 = snrm[w][j+5], n6 = snrm[w][j+6], n7 = snrm[w][j+7];
        acc.x += n0*v0.x + n1*v1.x + n2*v2.x + n3*v3.x + n4*v4.x + n5*v5.x + n6*v6.x + n7*v7.x;
        acc.y += n0*v0.y + n1*v1.y + n2*v2.y + n3*v3.y + n4*v4.y + n5*v5.y + n6*v6.y + n7*v7.y;
        acc.z += n0*v0.z + n1*v1.z + n2*v2.z + n3*v3.z + n4*v4.z + n5*v5.z + n6*v6.z + n7*v7.z;
        acc.w += n0*v0.w + n1*v1.w + n2*v2.w + n3*v3.w + n4*v4.w + n5*v5.w + n6*v6.w + n7*v7.w;
    }
    for (; j < cnt; j++) {
        float4 v = unpack_h4(*(const uint2*)(gl + ssrc[w][j]));
        float n0 = snrm[w][j];
        acc.x += n0*v.x; acc.y += n0*v.y; acc.z += n0*v.z; acc.w += n0*v.w;
    }

    if (MODE == 0) {
        ((uint2*)d_t1h)[(size_t)node * 32 + l] = pack_h4(acc);
        store_a4(1, node, l, acc);
    } else {
        float4 xv = ((const float4*)x)[(size_t)node * 32 + l];
        float4 t = make_float4(2.f*acc.x - xv.x, 2.f*acc.y - xv.y,
                               2.f*acc.z - xv.z, 2.f*acc.w - xv.w);
        store_a4(2, node, l, t);
    }
}

// ============ deep-ring mma.sync GEMM (fp16, MT=128, 16 slots) ===========
#define SA     0
#define SB     (SLOTS * ACH)               // 98304
#define S_BIAS (SB + SLOTS * BCH)          // 208896
#define S_MBF  (S_BIAS + 896)              // full barriers, 16 x 8B
#define S_MBE  (S_MBF + 128)               // empty barriers, 16 x 8B
#define S_TOTAL (S_MBE + 128)              // 210048

__device__ __forceinline__ void consume_chunk(uint32_t sb, int slot, int l,
                                              int mbase, int nbase,
                                              float acc[2][13][4]) {
    uint32_t a[2][4], bb[14][2];
    uint32_t aBase = sb + SA + slot * ACH;
#pragma unroll
    for (int i = 0; i < 2; i++)
        ldsm4(a[i], aBase + (mbase + i * 16 + (l & 15)) * AROW + (l >> 4) * 16);
    uint32_t bBase = sb + SB + slot * BCH + (l & 15) * BROW + (l >> 4) * 16;
#pragma unroll
    for (int j2 = 0; j2 < 7; j2++)
        ldsm4t(&bb[j2 * 2][0], bBase + (nbase + j2 * 16) * 2);
#pragma unroll
    for (int i = 0; i < 2; i++)
#pragma unroll
        for (int j = 0; j < 13; j++) mma16816(acc[i][j], a[i], bb[j]);
}

// issue the 2 bulk copies for global chunk index t into slot; single lane
__device__ __forceinline__ void issue_chunk(uint32_t sb, int t, int tile, int wbase) {
    int kb = t >> 3, c = t & 7;
    int slot = t & (SLOTS - 1);
    const char* ga  = (const char*)d_a[kb] + (size_t)tile * ATILE + c * ACH;
    const char* gb  = (const char*)d_wh[wbase + kb] + c * BCH;
    uint32_t mb = sb + S_MBF + slot * 8;
    MBARRIER_EXPECT_TX(mb, ACH + BCH);
    BULK_G2S(sb + SA + slot * ACH, ga, ACH, mb);
    BULK_G2S(sb + SB + slot * BCH, gb, BCH, mb);
}

__global__ __launch_bounds__(256, 1) void gemm_kernel(
    const float* __restrict__ bias, float* __restrict__ out, int nnodes, int s)
{
    extern __shared__ char smem[];
    const uint32_t sb = smem_u32(smem);
    const int tid = threadIdx.x;
    const int l = tid & 31;
    const int wid = tid >> 5;
    const int tile = blockIdx.x;
    const int bm = tile * MT;
    const int T = 8 * (s + 1);           // total chunks (8, 16, 24)
    const int wbase = s * (s + 1) / 2;
    float* sbias = (float*)(smem + S_BIAS);

    if (tid < OD) sbias[tid] = bias[tid];
    if (tid == 0) {
#pragma unroll
        for (int c = 0; c < SLOTS; c++) {
            MBARRIER_INIT(sb + S_MBF + c * 8, 1);   // full: tx-completed
            MBARRIER_INIT(sb + S_MBE + c * 8, 8);   // empty: one arrive per warp
        }
    }
    __syncthreads();

    const int P = (T < SLOTS) ? T : SLOTS;
    if (tid == 0)
        for (int t = 0; t < P; t++) issue_chunk(sb, t, tile, wbase);

    const int wm = wid >> 1, wn = wid & 1;
    const int mbase = wm * 32, nbase = wn * 104;

    float acc[2][13][4];
#pragma unroll
    for (int i = 0; i < 2; i++)
#pragma unroll
        for (int j = 0; j < 13; j++)
#pragma unroll
            for (int r = 0; r < 4; r++) acc[i][j][r] = 0.f;

    for (int t = 0; t < T; t++) {
        int slot = t & (SLOTS - 1);
        int use  = t >> 4;
        MBARRIER_WAIT_PARITY(sb + S_MBF + slot * 8, use & 1);
        consume_chunk(sb, slot, l, mbase, nbase, acc);
        __syncwarp();
        if (l == 0) MBARRIER_ARRIVE(sb + S_MBE + slot * 8);
        if (wid == 0 && t + SLOTS < T) {
            MBARRIER_WAIT_PARITY(sb + S_MBE + slot * 8, use & 1);
            if (l == 0) issue_chunk(sb, t + SLOTS, tile, wbase);
        }
        __syncwarp();
    }

    // epilogue
#pragma unroll
    for (int i = 0; i < 2; i++) {
        int row0 = bm + mbase + i * 16 + (l >> 2);
#pragma unroll
        for (int j = 0; j < 13; j++) {
            int col = nbase + j * 8 + (l & 3) * 2;
            if (col >= OD) continue;
            float bc0 = sbias[col], bc1 = sbias[col + 1];
            if (row0 < nnodes) {
                float2 v = make_float2(acc[i][j][0] + bc0, acc[i][j][1] + bc1);
                *(float2*)(out + ((size_t)s * nnodes + row0) * OD + col) = v;
            }
            int row1 = row0 + 8;
            if (row1 < nnodes) {
                float2 v = make_float2(acc[i][j][2] + bc0, acc[i][j][3] + bc1);
                *(float2*)(out + ((size_t)s * nnodes + row1) * OD + col) = v;
            }
        }
    }
}

static inline int cdiv(int a, int b) { return (a + b - 1) / b; }

extern "C" void kernel_launch(void* const* d_in, const int* in_sizes, int n_in,
                              void* d_out, int out_size) {
    const float* x    = (const float*)d_in[0];
    const int*   ei   = (const int*)  d_in[1];
    const float* ew   = (const float*)d_in[2];
    const float* w1_0 = (const float*)d_in[3];
    const float* b1   = (const float*)d_in[4];
    const float* w2_0 = (const float*)d_in[5];
    const float* w2_1 = (const float*)d_in[6];
    const float* b2   = (const float*)d_in[7];
    const float* w3_0 = (const float*)d_in[8];
    const float* w3_1 = (const float*)d_in[9];
    const float* w3_2 = (const float*)d_in[10];
    const float* b3   = (const float*)d_in[11];
    float* out = (float*)d_out;

    int E = in_sizes[2];
    int N = in_sizes[0] / FD;
    if (N > NN) N = NN;
    const int* src = ei;
    const int* dst = ei + E;

    static void* p_deg = nullptr;
    static void* p_cnt = nullptr;
    static cudaStream_t side = nullptr;
    static cudaEvent_t evPrep = nullptr, evSp0 = nullptr, evJoin = nullptr;
    if (!p_deg) {
        cudaFuncSetAttribute(gemm_kernel, cudaFuncAttributeMaxDynamicSharedMemorySize, S_TOTAL);
        cudaGetSymbolAddress(&p_deg, d_deg);
        cudaGetSymbolAddress(&p_cnt, d_cnt);
        cudaStreamCreateWithFlags(&side, cudaStreamNonBlocking);
        cudaEventCreateWithFlags(&evPrep, cudaEventDisableTiming);
        cudaEventCreateWithFlags(&evSp0, cudaEventDisableTiming);
        cudaEventCreateWithFlags(&evJoin, cudaEventDisableTiming);
    }

    cudaMemsetAsync(p_deg, 0, sizeof(float) * NN);
    cudaMemsetAsync(p_cnt, 0, sizeof(int) * NN);

    int degB = cdiv(E, 256);
    int cvtB = cdiv(N * 32, 256);
    int wprB = cdiv(6 * FD * BCOLS, 256);
    prep_kernel<<<degB + cvtB + wprB, 256>>>(src, ew, E, (const float4*)x, N * 32,
                                             w1_0, w2_0, w2_1, w3_0, w3_1, w3_2,
                                             degB, cvtB);
    cudaEventRecord(evPrep, 0);

    fill_kernel<<<cdiv(E, 256), 256>>>(src, dst, ew, E);
    spmm_kernel<0><<<cdiv(N, 8), 256>>>(x, N);
    cudaEventRecord(evSp0, 0);
    spmm_kernel<1><<<cdiv(N, 8), 256>>>(x, N);

    // side stream: s=0 GEMM after prep, s=1 GEMM after spmm<0>
    cudaStreamWaitEvent(side, evPrep, 0);
    gemm_kernel<<<NT, 256, S_TOTAL, side>>>(b1, out, N, 0);
    cudaStreamWaitEvent(side, evSp0, 0);
    gemm_kernel<<<NT, 256, S_TOTAL, side>>>(b2, out, N, 1);
    cudaEventRecord(evJoin, side);

    // main stream: s=2 GEMM after spmm<1>; join side before it completes the capture
    cudaStreamWaitEvent(0, evJoin, 0);
    gemm_kernel<<<NT, 256, S_TOTAL>>>(b3, out, N, 2);
}